// round 1
// baseline (speedup 1.0000x reference)
#include <cuda_runtime.h>

// Problem constants (hard-coded from reference)
#define Bn 64
#define Sn 512
#define Dn 512
#define Hn 512
#define NT 512

// Scratch: precomputed input-path projections: px[b,t,0:8]=W12@x, [8:16]=dW12@x
__device__ float g_px[Bn * Sn * 16];

__device__ __forceinline__ float sigf(float x) {
    // accurate-enough sigmoid: 1/(1+exp(-x)), __expf ~2^-21 rel err
    return __fdividef(1.0f, 1.0f + __expf(-x));
}
__device__ __forceinline__ float tanhf_fast(float x) {
    // tanh(x) = 2/(1+exp(-2x)) - 1
    return __fdividef(2.0f, 1.0f + __expf(-2.0f * x)) - 1.0f;
}

// ---------------------------------------------------------------------------
// Precompute Px = [W12; dW12] @ x[b,t,:]  for all (b,t).
// 256 blocks x 256 threads, each block owns 128 (b,t) pairs, weights in smem.
// ---------------------------------------------------------------------------
__global__ void __launch_bounds__(256) precompute_px(
    const float* __restrict__ x,
    const float* __restrict__ W12,
    const float* __restrict__ dW12)
{
    __shared__ float wxs[16 * 520];   // 16 rows, padded stride 520 (bank-conflict-free)
    __shared__ float xs[Dn];

    const int t = threadIdx.x;
    for (int i = t; i < 16 * Dn; i += 256) {
        int r = i >> 9, c = i & 511;
        float v = (r < 8) ? W12[r * Dn + c] : dW12[(r - 8) * Dn + c];
        wxs[r * 520 + c] = v;
    }
    __syncthreads();

    const int d = t >> 4;        // 16 dots
    const int sub = t & 15;      // 16 lanes per dot
    const int pairs_per_block = (Bn * Sn) / 256;  // 128
    const int base = blockIdx.x * pairs_per_block;

    for (int p = 0; p < pairs_per_block; p++) {
        const int bt = base + p;
        // coalesced load of x vector into smem
        const float2* xg = (const float2*)(x + (size_t)bt * Dn);
        ((float2*)xs)[t] = xg[t];
        __syncthreads();

        float acc = 0.0f;
        #pragma unroll
        for (int k = 0; k < 32; k++)
            acc = fmaf(wxs[d * 520 + sub + 16 * k], xs[sub + 16 * k], acc);
        #pragma unroll
        for (int off = 8; off; off >>= 1)
            acc += __shfl_xor_sync(0xffffffffu, acc, off);
        if (sub == 0) g_px[(size_t)bt * 16 + d] = acc;
        __syncthreads();
    }
}

// ---------------------------------------------------------------------------
// Sequential scan: 64 blocks (one per batch element) x 512 threads.
// Per step:
//   Phase A: 16 dots [U12;dU12] @ h1   (32 lanes/dot, weights in registers)
//   gates1 -> h1, c1
//   Phase B: 32 dots [W22;dW22]@h1_new, [U22;dU22]@h2  (16 lanes/dot)
//   gates2 -> h2, c2, write output
// ---------------------------------------------------------------------------
__global__ void __launch_bounds__(NT, 1) lstm_scan(
    const float* __restrict__ h0,  const float* __restrict__ c0,
    const float* __restrict__ W11, const float* __restrict__ U11,
    const float* __restrict__ dW11,const float* __restrict__ dU11,
    const float* __restrict__ U12, const float* __restrict__ dU12,
    const float* __restrict__ b11, const float* __restrict__ b12,
    const float* __restrict__ W21, const float* __restrict__ W22,
    const float* __restrict__ U21, const float* __restrict__ U22,
    const float* __restrict__ dW21,const float* __restrict__ dW22,
    const float* __restrict__ dU21,const float* __restrict__ dU22,
    const float* __restrict__ b21, const float* __restrict__ b22,
    float* __restrict__ out)
{
    __shared__ float h1_s[Hn];
    __shared__ float h2_s[Hn];
    __shared__ float dots1_s[16];
    __shared__ float dots2_s[32];
    __shared__ float pxs[16];

    const int t = threadIdx.x;
    const int b = blockIdx.x;
    const int h = t;                 // each thread owns one hidden index
    const int fidx = h & 7;
    const int hg = h >> 3;

    // --- state ---
    float c1 = c0[(size_t)b * Hn + h];
    float c2 = c0[(size_t)(Bn * Hn) + (size_t)b * Hn + h];
    h1_s[h] = h0[(size_t)b * Hn + h];
    h2_s[h] = h0[(size_t)(Bn * Hn) + (size_t)b * Hn + h];

    // --- loop-invariant per-thread gate constants (registers) ---
    float w1c[4], dw1c[4], u1c[4], du1c[4], bb1[4];
    float w2c[4], dw2c[4], u2c[4], du2c[4], bb2[4];
    #pragma unroll
    for (int s = 0; s < 4; s++) {
        const int grp = s * 64 + hg;
        w1c[s]  = W11[grp];  dw1c[s] = dW11[grp];
        u1c[s]  = U11[grp];  du1c[s] = dU11[grp];
        bb1[s]  = b11[s * Hn + h] + b12[s * Hn + h];
        w2c[s]  = W21[grp];  dw2c[s] = dW21[grp];
        u2c[s]  = U21[grp];  du2c[s] = dU21[grp];
        bb2[s]  = b21[s * Hn + h] + b22[s * Hn + h];
    }

    // --- Phase A weights in registers: dot dA = t>>5 (16 dots, 32 lanes) ---
    const int dA = t >> 5;
    const int laneA = t & 31;
    float4 wA[4];
    {
        const float* rp = (dA < 8) ? (U12 + dA * Hn) : (dU12 + (dA - 8) * Hn);
        const float4* rp4 = (const float4*)rp;
        #pragma unroll
        for (int k = 0; k < 4; k++) wA[k] = rp4[laneA + 32 * k];
    }

    // --- Phase B weights in registers: dot dB = t>>4 (32 dots, 16 lanes) ---
    const int dB = t >> 4;
    const int subB = t & 15;
    float4 wB[8];
    {
        const float* rowp;
        const int r = dB & 7;
        switch (dB >> 3) {
            case 0: rowp = W22  + r * Hn; break;
            case 1: rowp = dW22 + r * Hn; break;
            case 2: rowp = U22  + r * Hn; break;
            default: rowp = dU22 + r * Hn; break;
        }
        const float4* rp4 = (const float4*)rowp;
        #pragma unroll
        for (int k = 0; k < 8; k++) wB[k] = rp4[subB + 16 * k];
    }

    // prefetch first Px slice
    float pxreg = 0.0f;
    if (t < 16) pxreg = g_px[(size_t)(b * Sn) * 16 + t];

    __syncthreads();

    const size_t outbase = (size_t)b * Sn * Hn + h;

    for (int ts = 0; ts < Sn; ts++) {
        // publish this step's Px, then Phase A dots, then prefetch next Px
        if (t < 16) pxs[t] = pxreg;
        {
            const float4* h1v = (const float4*)h1_s;
            float acc = 0.0f;
            #pragma unroll
            for (int k = 0; k < 4; k++) {
                float4 hv = h1v[laneA + 32 * k];
                acc = fmaf(wA[k].x, hv.x, acc);
                acc = fmaf(wA[k].y, hv.y, acc);
                acc = fmaf(wA[k].z, hv.z, acc);
                acc = fmaf(wA[k].w, hv.w, acc);
            }
            #pragma unroll
            for (int off = 16; off; off >>= 1)
                acc += __shfl_xor_sync(0xffffffffu, acc, off);
            if (laneA == 0) dots1_s[dA] = acc;
        }
        if (t < 16 && ts + 1 < Sn)
            pxreg = g_px[(size_t)(b * Sn + ts + 1) * 16 + t];
        __syncthreads();   // S1

        // ---- gates layer 1 ----
        {
            const float P  = pxs[fidx];
            const float Q  = pxs[8 + fidx];
            const float R  = dots1_s[fidx];
            const float dR = dots1_s[8 + fidx];
            float gv[4];
            #pragma unroll
            for (int s = 0; s < 4; s++)
                gv[s] = fmaf(w1c[s], P,
                         fmaf(dw1c[s], Q,
                          fmaf(u1c[s], R,
                           fmaf(du1c[s], dR, bb1[s]))));
            const float ig = sigf(gv[0]);
            const float fg = sigf(gv[1]);
            const float gg = tanhf_fast(gv[2]);
            const float og = sigf(gv[3]);
            c1 = fmaf(fg, c1, ig * gg);
            h1_s[h] = og * tanhf_fast(c1);
        }
        __syncthreads();   // S2

        // ---- Phase B dots ----
        {
            const float4* src = (const float4*)((dB < 16) ? h1_s : h2_s);
            float acc = 0.0f;
            #pragma unroll
            for (int k = 0; k < 8; k++) {
                float4 hv = src[subB + 16 * k];
                acc = fmaf(wB[k].x, hv.x, acc);
                acc = fmaf(wB[k].y, hv.y, acc);
                acc = fmaf(wB[k].z, hv.z, acc);
                acc = fmaf(wB[k].w, hv.w, acc);
            }
            #pragma unroll
            for (int off = 8; off; off >>= 1)
                acc += __shfl_xor_sync(0xffffffffu, acc, off);
            if (subB == 0) dots2_s[dB] = acc;
        }
        __syncthreads();   // S3

        // ---- gates layer 2 + output ----
        {
            const float P  = dots2_s[fidx];
            const float Q  = dots2_s[8 + fidx];
            const float R  = dots2_s[16 + fidx];
            const float dR = dots2_s[24 + fidx];
            float gv[4];
            #pragma unroll
            for (int s = 0; s < 4; s++)
                gv[s] = fmaf(w2c[s], P,
                         fmaf(dw2c[s], Q,
                          fmaf(u2c[s], R,
                           fmaf(du2c[s], dR, bb2[s]))));
            const float ig = sigf(gv[0]);
            const float fg = sigf(gv[1]);
            const float gg = tanhf_fast(gv[2]);
            const float og = sigf(gv[3]);
            c2 = fmaf(fg, c2, ig * gg);
            const float h2v = og * tanhf_fast(c2);
            h2_s[h] = h2v;
            out[outbase + (size_t)ts * Hn] = h2v;
        }
        // no trailing sync needed: next writes are separated by S1/S2 barriers
    }

    // ---- final states: hn (2,B,H) then cn (2,B,H), after hidden_seq ----
    const size_t HS = (size_t)Bn * Sn * Hn;
    const size_t BH = (size_t)Bn * Hn;
    out[HS + (size_t)b * Hn + h]            = h1_s[h];
    out[HS + BH + (size_t)b * Hn + h]       = h2_s[h];
    out[HS + 2 * BH + (size_t)b * Hn + h]   = c1;
    out[HS + 3 * BH + (size_t)b * Hn + h]   = c2;
}

// ---------------------------------------------------------------------------
extern "C" void kernel_launch(void* const* d_in, const int* in_sizes, int n_in,
                              void* d_out, int out_size)
{
    // metadata order:
    // 0:x 1:h0 2:c0 3:W11 4:W12 5:U11 6:U12 7:dW11 8:dW12 9:dU11 10:dU12
    // 11:b11 12:b12 13:W21 14:W22 15:U21 16:U22 17:dW21 18:dW22 19:dU21
    // 20:dU22 21:b21 22:b22
    const float* x    = (const float*)d_in[0];
    const float* h0   = (const float*)d_in[1];
    const float* c0   = (const float*)d_in[2];
    const float* W11  = (const float*)d_in[3];
    const float* W12  = (const float*)d_in[4];
    const float* U11  = (const float*)d_in[5];
    const float* U12  = (const float*)d_in[6];
    const float* dW11 = (const float*)d_in[7];
    const float* dW12 = (const float*)d_in[8];
    const float* dU11 = (const float*)d_in[9];
    const float* dU12 = (const float*)d_in[10];
    const float* b11  = (const float*)d_in[11];
    const float* b12  = (const float*)d_in[12];
    const float* W21  = (const float*)d_in[13];
    const float* W22  = (const float*)d_in[14];
    const float* U21  = (const float*)d_in[15];
    const float* U22  = (const float*)d_in[16];
    const float* dW21 = (const float*)d_in[17];
    const float* dW22 = (const float*)d_in[18];
    const float* dU21 = (const float*)d_in[19];
    const float* dU22 = (const float*)d_in[20];
    const float* b21  = (const float*)d_in[21];
    const float* b22  = (const float*)d_in[22];
    float* out = (float*)d_out;

    precompute_px<<<256, 256>>>(x, W12, dW12);
    lstm_scan<<<Bn, NT>>>(h0, c0,
                          W11, U11, dW11, dU11, U12, dU12, b11, b12,
                          W21, W22, U21, U22, dW21, dW22, dU21, dU22, b21, b22,
                          out);
}

// round 2
// speedup vs baseline: 1.1500x; 1.1500x over previous
#include <cuda_runtime.h>

#define Bn 64
#define Sn 512
#define Dn 512
#define Hn 512
#define NT 512

__device__ __forceinline__ float tanh_ap(float x) {
    float y;
    asm("tanh.approx.f32 %0, %1;" : "=f"(y) : "f"(x));
    return y;
}
__device__ __forceinline__ float sig_ap(float x) {
    return fmaf(tanh_ap(0.5f * x), 0.5f, 0.5f);
}

// ---------------------------------------------------------------------------
// Fused kernel: 64 CTAs (one per batch element) x 512 threads.
// Per step, 3 barriers:
//   Seg1: warps 0-7:  A-dots  [U12;dU12]  @ h1_old   (2 dots/warp)
//         warps 8-15: X-dots  [W12;dW12]  @ x(ts)    (2 dots/warp)
//   Seg2: all: gates layer1 -> h1_new, c1;  plus B2-dots [U22;dU22] @ h2_old
//   Seg3: x(ts+1) STS into xs[cur^1]; B1-dots [W22;dW22] @ h1_new (1 dot/warp)
//   Seg4: gates layer2 -> h2_new, c2; store output
// ---------------------------------------------------------------------------
__global__ void __launch_bounds__(NT, 1) lstm_fused(
    const float* __restrict__ x,
    const float* __restrict__ h0,  const float* __restrict__ c0,
    const float* __restrict__ W11, const float* __restrict__ W12,
    const float* __restrict__ U11, const float* __restrict__ U12,
    const float* __restrict__ dW11,const float* __restrict__ dW12,
    const float* __restrict__ dU11,const float* __restrict__ dU12,
    const float* __restrict__ b11, const float* __restrict__ b12,
    const float* __restrict__ W21, const float* __restrict__ W22,
    const float* __restrict__ U21, const float* __restrict__ U22,
    const float* __restrict__ dW21,const float* __restrict__ dW22,
    const float* __restrict__ dU21,const float* __restrict__ dU22,
    const float* __restrict__ b21, const float* __restrict__ b22,
    float* __restrict__ out)
{
    __shared__ float h1_s[Hn];
    __shared__ float h2_s[Hn];
    __shared__ float xs[2][Dn];
    __shared__ float dots1_s[16];   // A dots
    __shared__ float pxd_s[16];     // X dots
    __shared__ float dots2_s[32];   // [0:16) B1, [16:32) B2
    __shared__ float4 gtab1[256];   // [hg*4+s] = (W11,dW11,U11,dU11)[s*64+hg]
    __shared__ float4 gtab2[256];

    const int t = threadIdx.x;
    const int b = blockIdx.x;
    const int w = t >> 5;
    const int l = t & 31;
    const int h = t;
    const int fidx = t & 7;
    const int hg = t >> 3;          // 0..63

    // ---- state ----
    float c1 = c0[(size_t)b * Hn + h];
    float c2 = c0[(size_t)(Bn * Hn) + (size_t)b * Hn + h];
    h1_s[h] = h0[(size_t)b * Hn + h];
    h2_s[h] = h0[(size_t)(Bn * Hn) + (size_t)b * Hn + h];

    // ---- gate constant tables in smem ----
    if (t < 256) {
        const int thg = t >> 2, s = t & 3;
        const int grp = s * 64 + thg;
        gtab1[t] = make_float4(W11[grp], dW11[grp], U11[grp], dU11[grp]);
        gtab2[t] = make_float4(W21[grp], dW21[grp], U21[grp], dU21[grp]);
    }

    // ---- per-thread biases ----
    float bb1[4], bb2[4];
    #pragma unroll
    for (int s = 0; s < 4; s++) {
        bb1[s] = b11[s * Hn + h] + b12[s * Hn + h];
        bb2[s] = b21[s * Hn + h] + b22[s * Hn + h];
    }

    // ---- Seg1 weights: 2 dot rows per warp ----
    float4 wS1[8];
    {
        const float* r0;
        const float* r1;
        if (w < 8) {
            const int d0 = 2 * w, d1 = d0 + 1;
            r0 = (d0 < 8) ? (U12 + d0 * Hn) : (dU12 + (d0 - 8) * Hn);
            r1 = (d1 < 8) ? (U12 + d1 * Hn) : (dU12 + (d1 - 8) * Hn);
        } else {
            const int d0 = 2 * (w - 8), d1 = d0 + 1;
            r0 = (d0 < 8) ? (W12 + d0 * Dn) : (dW12 + (d0 - 8) * Dn);
            r1 = (d1 < 8) ? (W12 + d1 * Dn) : (dW12 + (d1 - 8) * Dn);
        }
        const float4* r04 = (const float4*)r0;
        const float4* r14 = (const float4*)r1;
        #pragma unroll
        for (int j = 0; j < 4; j++) {
            wS1[j]     = r04[l + 32 * j];
            wS1[4 + j] = r14[l + 32 * j];
        }
    }

    // ---- B2 weights: dot w over h2 ----
    float4 wB2[4];
    {
        const float* rp = (w < 8) ? (U22 + w * Hn) : (dU22 + (w - 8) * Hn);
        const float4* rp4 = (const float4*)rp;
        #pragma unroll
        for (int j = 0; j < 4; j++) wB2[j] = rp4[l + 32 * j];
    }

    // ---- B1 weights: dot w over h1_new ----
    float4 wB1[4];
    {
        const float* rp = (w < 8) ? (W22 + w * Hn) : (dW22 + (w - 8) * Hn);
        const float4* rp4 = (const float4*)rp;
        #pragma unroll
        for (int j = 0; j < 4; j++) wB1[j] = rp4[l + 32 * j];
    }

    // ---- x(0) into xs[0]; prefetch x(1) into reg ----
    const size_t xbase = (size_t)b * Sn * Dn;
    xs[0][t] = x[xbase + t];
    float xpre = x[xbase + Dn + t];

    __syncthreads();

    const size_t outbase = (size_t)b * Sn * Hn + h;
    int cur = 0;

    for (int ts = 0; ts < Sn; ts++) {
        // ================= Seg1: A-dots / X-dots =================
        {
            const float4* src = (w < 8) ? (const float4*)h1_s
                                        : (const float4*)xs[cur];
            float a0 = 0.f, a1 = 0.f, b0 = 0.f, b1v = 0.f;
            #pragma unroll
            for (int j = 0; j < 4; j += 2) {
                const float4 v = src[l + 32 * j];
                const float4 u = src[l + 32 * (j + 1)];
                a0  = fmaf(wS1[j].x, v.x, a0);
                a0  = fmaf(wS1[j].y, v.y, a0);
                a0  = fmaf(wS1[j].z, v.z, a0);
                a0  = fmaf(wS1[j].w, v.w, a0);
                b0  = fmaf(wS1[j + 1].x, u.x, b0);
                b0  = fmaf(wS1[j + 1].y, u.y, b0);
                b0  = fmaf(wS1[j + 1].z, u.z, b0);
                b0  = fmaf(wS1[j + 1].w, u.w, b0);
                a1  = fmaf(wS1[4 + j].x, v.x, a1);
                a1  = fmaf(wS1[4 + j].y, v.y, a1);
                a1  = fmaf(wS1[4 + j].z, v.z, a1);
                a1  = fmaf(wS1[4 + j].w, v.w, a1);
                b1v = fmaf(wS1[4 + j + 1].x, u.x, b1v);
                b1v = fmaf(wS1[4 + j + 1].y, u.y, b1v);
                b1v = fmaf(wS1[4 + j + 1].z, u.z, b1v);
                b1v = fmaf(wS1[4 + j + 1].w, u.w, b1v);
            }
            a0 += b0;
            a1 += b1v;
            #pragma unroll
            for (int off = 16; off; off >>= 1) {
                a0 += __shfl_xor_sync(0xffffffffu, a0, off);
                a1 += __shfl_xor_sync(0xffffffffu, a1, off);
            }
            if (l == 0) {
                if (w < 8) {
                    dots1_s[2 * w]     = a0;
                    dots1_s[2 * w + 1] = a1;
                } else {
                    pxd_s[2 * (w - 8)]     = a0;
                    pxd_s[2 * (w - 8) + 1] = a1;
                }
            }
        }
        __syncthreads();   // S1

        // ================= Seg2: B2-dot + gates layer 1 =================
        {
            // B2 dot first: its FMA/shfl overlaps the MUFU chain below
            const float4* src2 = (const float4*)h2_s;
            float aB = 0.f, bB = 0.f;
            #pragma unroll
            for (int j = 0; j < 4; j += 2) {
                const float4 v = src2[l + 32 * j];
                const float4 u = src2[l + 32 * (j + 1)];
                aB = fmaf(wB2[j].x, v.x, aB);
                aB = fmaf(wB2[j].y, v.y, aB);
                aB = fmaf(wB2[j].z, v.z, aB);
                aB = fmaf(wB2[j].w, v.w, aB);
                bB = fmaf(wB2[j + 1].x, u.x, bB);
                bB = fmaf(wB2[j + 1].y, u.y, bB);
                bB = fmaf(wB2[j + 1].z, u.z, bB);
                bB = fmaf(wB2[j + 1].w, u.w, bB);
            }
            aB += bB;
            #pragma unroll
            for (int off = 16; off; off >>= 1)
                aB += __shfl_xor_sync(0xffffffffu, aB, off);
            if (l == 0) dots2_s[16 + w] = aB;

            // gates layer 1
            const float P  = pxd_s[fidx];
            const float Q  = pxd_s[8 + fidx];
            const float R  = dots1_s[fidx];
            const float dR = dots1_s[8 + fidx];
            float gv[4];
            #pragma unroll
            for (int s = 0; s < 4; s++) {
                const float4 gw = gtab1[hg * 4 + s];
                gv[s] = fmaf(gw.x, P,
                         fmaf(gw.y, Q,
                          fmaf(gw.z, R,
                           fmaf(gw.w, dR, bb1[s]))));
            }
            const float ig = sig_ap(gv[0]);
            const float fg = sig_ap(gv[1]);
            const float gg = tanh_ap(gv[2]);
            const float og = sig_ap(gv[3]);
            c1 = fmaf(fg, c1, ig * gg);
            h1_s[h] = og * tanh_ap(c1);
        }
        __syncthreads();   // S2

        // ================= Seg3: x prefetch STS + B1-dot =================
        xs[cur ^ 1][t] = xpre;
        if (ts + 2 < Sn) xpre = x[xbase + (size_t)(ts + 2) * Dn + t];
        {
            const float4* src1 = (const float4*)h1_s;
            float aB = 0.f, bB = 0.f;
            #pragma unroll
            for (int j = 0; j < 4; j += 2) {
                const float4 v = src1[l + 32 * j];
                const float4 u = src1[l + 32 * (j + 1)];
                aB = fmaf(wB1[j].x, v.x, aB);
                aB = fmaf(wB1[j].y, v.y, aB);
                aB = fmaf(wB1[j].z, v.z, aB);
                aB = fmaf(wB1[j].w, v.w, aB);
                bB = fmaf(wB1[j + 1].x, u.x, bB);
                bB = fmaf(wB1[j + 1].y, u.y, bB);
                bB = fmaf(wB1[j + 1].z, u.z, bB);
                bB = fmaf(wB1[j + 1].w, u.w, bB);
            }
            aB += bB;
            #pragma unroll
            for (int off = 16; off; off >>= 1)
                aB += __shfl_xor_sync(0xffffffffu, aB, off);
            if (l == 0) dots2_s[w] = aB;
        }
        __syncthreads();   // S3

        // ================= Seg4: gates layer 2 + output =================
        {
            const float P  = dots2_s[fidx];
            const float Q  = dots2_s[8 + fidx];
            const float R  = dots2_s[16 + fidx];
            const float dR = dots2_s[24 + fidx];
            float gv[4];
            #pragma unroll
            for (int s = 0; s < 4; s++) {
                const float4 gw = gtab2[hg * 4 + s];
                gv[s] = fmaf(gw.x, P,
                         fmaf(gw.y, Q,
                          fmaf(gw.z, R,
                           fmaf(gw.w, dR, bb2[s]))));
            }
            const float ig = sig_ap(gv[0]);
            const float fg = sig_ap(gv[1]);
            const float gg = tanh_ap(gv[2]);
            const float og = sig_ap(gv[3]);
            c2 = fmaf(fg, c2, ig * gg);
            const float h2v = og * tanh_ap(c2);
            h2_s[h] = h2v;
            out[outbase + (size_t)ts * Hn] = h2v;
        }
        cur ^= 1;
        // Seg4 -> Seg1(next) needs no barrier: Seg1 touches only
        // h1_s (stable since S2) and xs[cur] (stable since S3).
    }

    // ---- final states: hn (2,B,H) then cn (2,B,H) ----
    const size_t HS = (size_t)Bn * Sn * Hn;
    const size_t BH = (size_t)Bn * Hn;
    out[HS + (size_t)b * Hn + h]          = h1_s[h];
    out[HS + BH + (size_t)b * Hn + h]     = h2_s[h];
    out[HS + 2 * BH + (size_t)b * Hn + h] = c1;
    out[HS + 3 * BH + (size_t)b * Hn + h] = c2;
}

// ---------------------------------------------------------------------------
extern "C" void kernel_launch(void* const* d_in, const int* in_sizes, int n_in,
                              void* d_out, int out_size)
{
    const float* x    = (const float*)d_in[0];
    const float* h0   = (const float*)d_in[1];
    const float* c0   = (const float*)d_in[2];
    const float* W11  = (const float*)d_in[3];
    const float* W12  = (const float*)d_in[4];
    const float* U11  = (const float*)d_in[5];
    const float* U12  = (const float*)d_in[6];
    const float* dW11 = (const float*)d_in[7];
    const float* dW12 = (const float*)d_in[8];
    const float* dU11 = (const float*)d_in[9];
    const float* dU12 = (const float*)d_in[10];
    const float* b11  = (const float*)d_in[11];
    const float* b12  = (const float*)d_in[12];
    const float* W21  = (const float*)d_in[13];
    const float* W22  = (const float*)d_in[14];
    const float* U21  = (const float*)d_in[15];
    const float* U22  = (const float*)d_in[16];
    const float* dW21 = (const float*)d_in[17];
    const float* dW22 = (const float*)d_in[18];
    const float* dU21 = (const float*)d_in[19];
    const float* dU22 = (const float*)d_in[20];
    const float* b21  = (const float*)d_in[21];
    const float* b22  = (const float*)d_in[22];
    float* out = (float*)d_out;

    lstm_fused<<<Bn, NT>>>(x, h0, c0,
                           W11, W12, U11, U12, dW11, dW12, dU11, dU12, b11, b12,
                           W21, W22, U21, U22, dW21, dW22, dU21, dU22, b21, b22,
                           out);
}

// round 3
// speedup vs baseline: 1.3228x; 1.1503x over previous
#include <cuda_runtime.h>

typedef unsigned long long ull;

#define Bn 64
#define Sn 512
#define Hn 512

// ---------------- packed f32x2 + approx-activation helpers ----------------
__device__ __forceinline__ ull fma2(ull a, ull b, ull c) {
    ull d;
    asm("fma.rn.f32x2 %0, %1, %2, %3;" : "=l"(d) : "l"(a), "l"(b), "l"(c));
    return d;
}
__device__ __forceinline__ ull add2(ull a, ull b) {
    ull d;
    asm("add.rn.f32x2 %0, %1, %2;" : "=l"(d) : "l"(a), "l"(b));
    return d;
}
__device__ __forceinline__ ull pk2(float lo, float hi) {
    ull r;
    asm("mov.b64 %0, {%1, %2};" : "=l"(r) : "f"(lo), "f"(hi));
    return r;
}
__device__ __forceinline__ void upk2(ull v, float& lo, float& hi) {
    asm("mov.b64 {%0, %1}, %2;" : "=f"(lo), "=f"(hi) : "l"(v));
}
__device__ __forceinline__ float tanh_ap(float x) {
    float y;
    asm("tanh.approx.f32 %0, %1;" : "=f"(y) : "f"(x));
    return y;
}
__device__ __forceinline__ float sig_ap(float x) {
    return fmaf(tanh_ap(0.5f * x), 0.5f, 0.5f);
}

// ---------------- 4-dot register-blocked dot product ----------------
struct DotW { ull lo[4][4]; ull hi[4][4]; };

__device__ __forceinline__ void run_dots(const DotW& W,
                                         const ulonglong2* __restrict__ src,
                                         ull* __restrict__ dst4, int l)
{
    ull aL0 = 0, aL1 = 0, aL2 = 0, aL3 = 0;
    ull aH0 = 0, aH1 = 0, aH2 = 0, aH3 = 0;
    #pragma unroll
    for (int j = 0; j < 4; j++) {
        const ulonglong2 v = src[l + 32 * j];
        aL0 = fma2(W.lo[0][j], v.x, aL0);  aH0 = fma2(W.hi[0][j], v.y, aH0);
        aL1 = fma2(W.lo[1][j], v.x, aL1);  aH1 = fma2(W.hi[1][j], v.y, aH1);
        aL2 = fma2(W.lo[2][j], v.x, aL2);  aH2 = fma2(W.hi[2][j], v.y, aH2);
        aL3 = fma2(W.lo[3][j], v.x, aL3);  aH3 = fma2(W.hi[3][j], v.y, aH3);
    }
    float d0, d1, d2, d3;
    { float lo, hi; upk2(add2(aL0, aH0), lo, hi); d0 = lo + hi; }
    { float lo, hi; upk2(add2(aL1, aH1), lo, hi); d1 = lo + hi; }
    { float lo, hi; upk2(add2(aL2, aH2), lo, hi); d2 = lo + hi; }
    { float lo, hi; upk2(add2(aL3, aH3), lo, hi); d3 = lo + hi; }

    // merged 4-way reduction tree: 9 shfl total
    d0 += __shfl_xor_sync(0xffffffffu, d0, 16);
    d1 += __shfl_xor_sync(0xffffffffu, d1, 16);
    d2 += __shfl_xor_sync(0xffffffffu, d2, 16);
    d3 += __shfl_xor_sync(0xffffffffu, d3, 16);
    float v02 = (l & 16) ? d2 : d0;
    float v13 = (l & 16) ? d3 : d1;
    v02 += __shfl_xor_sync(0xffffffffu, v02, 8);
    v13 += __shfl_xor_sync(0xffffffffu, v13, 8);
    float wv = (l & 8) ? v13 : v02;
    wv += __shfl_xor_sync(0xffffffffu, wv, 4);
    wv += __shfl_xor_sync(0xffffffffu, wv, 2);
    wv += __shfl_xor_sync(0xffffffffu, wv, 1);
    if ((l & 7) == 0) dst4[l >> 3] = pk2(wv, wv);   // duplicated for bcast LDS.64
}

// ---------------- gate evaluation (2 hidden units, packed preact) ----------
__device__ __forceinline__ void gates_eval(const ull* __restrict__ cp,
                                           const ull* __restrict__ dA,
                                           const ull* __restrict__ dB,
                                           const ull bb[4], int f8,
                                           float& ca, float& cb,
                                           float& ha, float& hb)
{
    const ull P  = dA[f8];
    const ull Q  = dA[8 + f8];
    const ull R  = dB[f8];
    const ull dR = dB[8 + f8];
    ull g0 = fma2(cp[0],  P, fma2(cp[1],  Q, fma2(cp[2],  R, fma2(cp[3],  dR, bb[0]))));
    ull g1 = fma2(cp[4],  P, fma2(cp[5],  Q, fma2(cp[6],  R, fma2(cp[7],  dR, bb[1]))));
    ull g2 = fma2(cp[8],  P, fma2(cp[9],  Q, fma2(cp[10], R, fma2(cp[11], dR, bb[2]))));
    ull g3 = fma2(cp[12], P, fma2(cp[13], Q, fma2(cp[14], R, fma2(cp[15], dR, bb[3]))));
    float ia_, ib_, fa_, fb_, ga_, gb_, oa_, ob_;
    upk2(g0, ia_, ib_);
    upk2(g1, fa_, fb_);
    upk2(g2, ga_, gb_);
    upk2(g3, oa_, ob_);
    const float ia = sig_ap(ia_), ib = sig_ap(ib_);
    const float fa = sig_ap(fa_), fb = sig_ap(fb_);
    const float ga = tanh_ap(ga_), gb = tanh_ap(gb_);
    const float oa = sig_ap(oa_), ob = sig_ap(ob_);
    ca = fmaf(fa, ca, ia * ga);
    cb = fmaf(fb, cb, ib * gb);
    ha = oa * tanh_ap(ca);
    hb = ob * tanh_ap(cb);
}

// ---------------------------------------------------------------------------
// Staggered 2-layer LSTM scan. 64 CTAs x 512 threads.
// Warps 0-7  = layer-1 group: phase A -> dots (x & h1), phase B -> gates.
// Warps 8-15 = layer-2 group: phase A -> gates,          phase B -> dots.
// Layer 2 lags layer 1 by one timestep.
// ---------------------------------------------------------------------------
__global__ void __launch_bounds__(512, 1) lstm_stag(
    const float* __restrict__ x,
    const float* __restrict__ h0,  const float* __restrict__ c0,
    const float* __restrict__ W11, const float* __restrict__ W12,
    const float* __restrict__ U11, const float* __restrict__ U12,
    const float* __restrict__ dW11,const float* __restrict__ dW12,
    const float* __restrict__ dU11,const float* __restrict__ dU12,
    const float* __restrict__ b11, const float* __restrict__ b12,
    const float* __restrict__ W21, const float* __restrict__ W22,
    const float* __restrict__ U21, const float* __restrict__ U22,
    const float* __restrict__ dW21,const float* __restrict__ dW22,
    const float* __restrict__ dU21,const float* __restrict__ dU22,
    const float* __restrict__ b21, const float* __restrict__ b22,
    float* __restrict__ out)
{
    __shared__ __align__(16) float h1s[2][Hn];
    __shared__ __align__(16) float h2s[Hn];
    __shared__ __align__(16) float xs[2][Hn];
    __shared__ ull xdotp[16], adotp[16], b1dotp[16], b2dotp[16];
    __shared__ ull g1p[512], g2p[512];

    const int t = threadIdx.x;
    const int b = blockIdx.x;
    const int w = t >> 5;
    const int l = t & 31;
    const bool isL1 = (t < 256);
    const int tt = t & 255;

    // ---------------- init shared state ----------------
    h1s[1][t] = h0[(size_t)b * Hn + t];
    h2s[t]    = h0[(size_t)Bn * Hn + (size_t)b * Hn + t];
    xs[0][t]  = x[(size_t)b * Sn * Hn + t];

    {
        const int hg = t >> 4, s = (t >> 2) & 3, c = t & 3;
        const int glo = s * 64 + hg, ghi = glo + 32;
        const float* t1 = (c == 0) ? W11 : (c == 1) ? dW11 : (c == 2) ? U11 : dU11;
        const float* t2 = (c == 0) ? W21 : (c == 1) ? dW21 : (c == 2) ? U21 : dU21;
        g1p[t] = pk2(t1[glo], t1[ghi]);
        g2p[t] = pk2(t2[glo], t2[ghi]);
    }

    // ---------------- per-thread constants ----------------
    ull bb[4];
    float ca, cb;
    if (isL1) {
        #pragma unroll
        for (int s = 0; s < 4; s++)
            bb[s] = pk2(b11[s * Hn + tt] + b12[s * Hn + tt],
                        b11[s * Hn + tt + 256] + b12[s * Hn + tt + 256]);
        ca = c0[(size_t)b * Hn + tt];
        cb = c0[(size_t)b * Hn + tt + 256];
    } else {
        #pragma unroll
        for (int s = 0; s < 4; s++)
            bb[s] = pk2(b21[s * Hn + tt] + b22[s * Hn + tt],
                        b21[s * Hn + tt + 256] + b22[s * Hn + tt + 256]);
        ca = c0[(size_t)Bn * Hn + (size_t)b * Hn + tt];
        cb = c0[(size_t)Bn * Hn + (size_t)b * Hn + tt + 256];
    }

    // ---------------- dot weights in registers ----------------
    DotW W;
    {
        const float* m;
        int rb;
        if (isL1) {
            const int sel = w >> 1;
            rb = 4 * (w & 1);
            m = (sel == 0) ? W12 : (sel == 1) ? dW12 : (sel == 2) ? U12 : dU12;
        } else {
            const int w8 = w - 8;
            const int sel = w8 >> 1;
            rb = 4 * (w8 & 1);
            m = (sel == 0) ? W22 : (sel == 1) ? dW22 : (sel == 2) ? U22 : dU22;
        }
        #pragma unroll
        for (int r = 0; r < 4; r++) {
            const ulonglong2* rp = (const ulonglong2*)(m + (size_t)(rb + r) * Hn);
            #pragma unroll
            for (int j = 0; j < 4; j++) {
                const ulonglong2 tmp = rp[l + 32 * j];
                W.lo[r][j] = tmp.x;
                W.hi[r][j] = tmp.y;
            }
        }
    }

    ull* dots_dst = (w < 4)  ? (xdotp  + 4 * w)
                  : (w < 8)  ? (adotp  + 4 * (w - 4))
                  : (w < 12) ? (b1dotp + 4 * (w - 8))
                             : (b2dotp + 4 * (w - 12));

    const ull* xg = (const ull*)(x + (size_t)b * Sn * Hn);
    ull xpre = 0;
    if (isL1) xpre = xg[256 + tt];   // x[1]

    __syncthreads();

    const int f8 = tt & 7;
    const int hg0 = tt >> 3;
    const ull* cp = (isL1 ? g1p : g2p) + hg0 * 16;
    float* outb = out + (size_t)b * Sn * Hn;

    for (int i = 0; i <= 513; i++) {
        // ================= Phase A =================
        if (isL1) {
            if (i < 512) {
                const ulonglong2* src = (const ulonglong2*)
                    ((w < 4) ? xs[i & 1] : h1s[(i + 1) & 1]);
                run_dots(W, src, dots_dst, l);
            }
        } else if (i >= 2) {
            float ha, hb;
            gates_eval(cp, b1dotp, b2dotp, bb, f8, ca, cb, ha, hb);
            h2s[tt] = ha;
            h2s[tt + 256] = hb;
            const size_t ob = (size_t)(i - 2) * Hn;
            outb[ob + tt] = ha;
            outb[ob + tt + 256] = hb;
        }
        __syncthreads();

        // ================= Phase B =================
        if (isL1) {
            if (i < 512) {
                float ha, hb;
                gates_eval(cp, xdotp, adotp, bb, f8, ca, cb, ha, hb);
                float* hbuf = h1s[i & 1];
                hbuf[tt] = ha;
                hbuf[tt + 256] = hb;
                if (i < 511) ((ull*)xs[(i + 1) & 1])[tt] = xpre;
                const int nx = (i + 2 < 511) ? (i + 2) : 511;
                xpre = xg[(size_t)nx * 256 + tt];
            }
        } else if (i >= 1 && i <= 512) {
            const ulonglong2* src = (const ulonglong2*)
                ((w < 12) ? h1s[(i + 1) & 1] : h2s);
            run_dots(W, src, dots_dst, l);
        }
        __syncthreads();
    }

    // ---------------- final states: hn (2,B,H), cn (2,B,H) ----------------
    const size_t HS = (size_t)Bn * Sn * Hn;
    const size_t BH = (size_t)Bn * Hn;
    if (isL1) {
        out[HS + (size_t)b * Hn + tt]              = h1s[1][tt];
        out[HS + (size_t)b * Hn + tt + 256]        = h1s[1][tt + 256];
        out[HS + 2 * BH + (size_t)b * Hn + tt]       = ca;
        out[HS + 2 * BH + (size_t)b * Hn + tt + 256] = cb;
    } else {
        out[HS + BH + (size_t)b * Hn + tt]           = h2s[tt];
        out[HS + BH + (size_t)b * Hn + tt + 256]     = h2s[tt + 256];
        out[HS + 3 * BH + (size_t)b * Hn + tt]       = ca;
        out[HS + 3 * BH + (size_t)b * Hn + tt + 256] = cb;
    }
}

// ---------------------------------------------------------------------------
extern "C" void kernel_launch(void* const* d_in, const int* in_sizes, int n_in,
                              void* d_out, int out_size)
{
    const float* x    = (const float*)d_in[0];
    const float* h0   = (const float*)d_in[1];
    const float* c0   = (const float*)d_in[2];
    const float* W11  = (const float*)d_in[3];
    const float* W12  = (const float*)d_in[4];
    const float* U11  = (const float*)d_in[5];
    const float* U12  = (const float*)d_in[6];
    const float* dW11 = (const float*)d_in[7];
    const float* dW12 = (const float*)d_in[8];
    const float* dU11 = (const float*)d_in[9];
    const float* dU12 = (const float*)d_in[10];
    const float* b11  = (const float*)d_in[11];
    const float* b12  = (const float*)d_in[12];
    const float* W21  = (const float*)d_in[13];
    const float* W22  = (const float*)d_in[14];
    const float* U21  = (const float*)d_in[15];
    const float* U22  = (const float*)d_in[16];
    const float* dW21 = (const float*)d_in[17];
    const float* dW22 = (const float*)d_in[18];
    const float* dU21 = (const float*)d_in[19];
    const float* dU22 = (const float*)d_in[20];
    const float* b21  = (const float*)d_in[21];
    const float* b22  = (const float*)d_in[22];
    float* out = (float*)d_out;

    lstm_stag<<<Bn, 512>>>(x, h0, c0,
                           W11, W12, U11, U12, dW11, dW12, dU11, dU12, b11, b12,
                           W21, W22, U21, U22, dW21, dW22, dU21, dU22, b21, b22,
                           out);
}